// round 7
// baseline (speedup 1.0000x reference)
#include <cuda_runtime.h>
#include <cuda_fp16.h>
#include <math.h>
#include <stdint.h>

#define BATCH 32
#define CIN   256
#define COUT  256
#define NEXP  4
#define HH    56
#define WW    56
#define HWSZ  3136

#define PADW    58
#define QCNT    3364           // 58*58 padded positions
#define GUARD   64
#define ROWSPAD 3712           // GUARD + 28*128 + GUARD
#define MTILES  27             // ceil(3364/128)

// ---------------------------------------------------------------------------
// Scratch (__device__ globals zero-initialized; guard/border rows stay 0)
// ---------------------------------------------------------------------------
__device__ float g_pooled[BATCH * CIN];
__device__ float g_att[BATCH * NEXP];
__device__ __half g_xt[(size_t)BATCH * ROWSPAD * CIN];
__device__ __half g_wf[(size_t)BATCH * 9 * COUT * CIN];

// ---------------------------------------------------------------------------
// PTX helpers (compute_80-era: valid on compute_103 base target)
// ---------------------------------------------------------------------------
__device__ __forceinline__ uint32_t smem_u32(const void* p) {
    uint32_t a;
    asm("{ .reg .u64 t; cvta.to.shared.u64 t, %1; cvt.u32.u64 %0, t; }"
        : "=r"(a) : "l"(p));
    return a;
}
#define CP_ASYNC16(dst, src) \
    asm volatile("cp.async.cg.shared.global [%0], [%1], 16;" \
                 :: "r"(dst), "l"(src) : "memory")
#define CP_COMMIT() asm volatile("cp.async.commit_group;" ::: "memory")
#define CP_WAIT0()  asm volatile("cp.async.wait_group 0;" ::: "memory")
#define CP_WAIT1()  asm volatile("cp.async.wait_group 1;" ::: "memory")

#define LDSM4(r, addr) \
    asm volatile("ldmatrix.sync.aligned.m8n8.x4.shared.b16 {%0,%1,%2,%3}, [%4];" \
                 : "=r"((r)[0]), "=r"((r)[1]), "=r"((r)[2]), "=r"((r)[3]) \
                 : "r"(addr))

#define MMA16816(d, a, b0, b1) \
    asm volatile("mma.sync.aligned.m16n8k16.row.col.f32.f16.f16.f32 " \
                 "{%0,%1,%2,%3}, {%4,%5,%6,%7}, {%8,%9}, {%0,%1,%2,%3};" \
                 : "+f"((d)[0]), "+f"((d)[1]), "+f"((d)[2]), "+f"((d)[3]) \
                 : "r"((a)[0]), "r"((a)[1]), "r"((a)[2]), "r"((a)[3]), \
                   "r"(b0), "r"(b1))

// ---------------------------------------------------------------------------
// Kernel 1: per-(b,c) spatial mean
// ---------------------------------------------------------------------------
__global__ void mean_kernel(const float* __restrict__ x) {
    int bc = blockIdx.x;
    const float4* p = reinterpret_cast<const float4*>(x + (size_t)bc * HWSZ);
    float s = 0.f;
    for (int i = threadIdx.x; i < HWSZ / 4; i += 256) {
        float4 v = p[i];
        s += (v.x + v.y) + (v.z + v.w);
    }
    #pragma unroll
    for (int o = 16; o; o >>= 1) s += __shfl_xor_sync(0xffffffffu, s, o);
    __shared__ float ws[8];
    if ((threadIdx.x & 31) == 0) ws[threadIdx.x >> 5] = s;
    __syncthreads();
    if (threadIdx.x == 0) {
        float t = 0.f;
        #pragma unroll
        for (int i = 0; i < 8; i++) t += ws[i];
        g_pooled[bc] = t * (1.0f / (float)HWSZ);
    }
}

// ---------------------------------------------------------------------------
// Kernel 2: att = sigmoid(pooled @ att_w^T)
// ---------------------------------------------------------------------------
__global__ void att_kernel(const float* __restrict__ att_w) {
    int idx = threadIdx.x;
    int b = idx >> 2, k = idx & 3;
    const float* pr = g_pooled + b * CIN;
    const float* wr = att_w + k * CIN;
    float s = 0.f;
    #pragma unroll 8
    for (int c = 0; c < CIN; c++) s += pr[c] * wr[c];
    g_att[idx] = 1.0f / (1.0f + expf(-s));
}

// ---------------------------------------------------------------------------
// Kernel 3: aggregate weights -> fp16, layout [b][t][cout][ci]
// ---------------------------------------------------------------------------
__global__ void wprep_kernel(const float* __restrict__ weight) {
    int o = blockIdx.x, b = blockIdx.y, ci = threadIdx.x;
    float a[NEXP];
    #pragma unroll
    for (int k = 0; k < NEXP; k++) a[k] = g_att[b * NEXP + k];
    #pragma unroll
    for (int t = 0; t < 9; t++) {
        float v = 0.f;
        #pragma unroll
        for (int k = 0; k < NEXP; k++)
            v += a[k] * weight[(((size_t)k * COUT + o) * CIN + ci) * 9 + t];
        size_t p = (((size_t)b * 9 + t) * COUT + o) * CIN + ci;
        g_wf[p] = __float2half_rn(v);
    }
}

// ---------------------------------------------------------------------------
// Kernel 4: transpose x -> padded position-major fp16
// ---------------------------------------------------------------------------
__global__ void __launch_bounds__(256) transpose_kernel(const float* __restrict__ x) {
    __shared__ float tile[64][33];
    int b   = blockIdx.z;
    int ci0 = blockIdx.y * 64;
    int p0  = blockIdx.x * 32;
    int tid = threadIdx.x;
    int px = tid & 31, cir = tid >> 5;
    #pragma unroll
    for (int i = 0; i < 8; i++) {
        int ci = cir * 8 + i;
        tile[ci][px] = x[((size_t)b * CIN + ci0 + ci) * HWSZ + p0 + px];
    }
    __syncthreads();
    int cc = tid & 7, r = tid >> 3;
    int p = p0 + r;
    int h = p / WW, w = p % WW;
    size_t row = (size_t)b * ROWSPAD + GUARD + (size_t)(h + 1) * PADW + (w + 1);
    __align__(16) __half h8[8];
    #pragma unroll
    for (int j = 0; j < 8; j++)
        h8[j] = __float2half_rn(tile[cc * 8 + j][r]);
    *reinterpret_cast<uint4*>(g_xt + row * CIN + ci0 + cc * 8) =
        *reinterpret_cast<const uint4*>(h8);
}

// ---------------------------------------------------------------------------
// Kernel 5: implicit-GEMM conv, pure fp16 mma.sync (single combo).
// CTA tile: M=128 positions x N=256 couts, 512 threads (16 warps = 4M x 4N).
// A (x) staged once per ci-chunk as a 256-row halo; all 9 taps are row
// offsets into the resident halo. B (w) double-buffered per (chunk,tap).
// SMEM: A 32KB | B 2x32KB = 96KB -> 2 CTAs/SM.
// ---------------------------------------------------------------------------
#define A_BYTES   32768
#define B_STG     32768
#define SMEM_BYTES_MMA (A_BYTES + 2 * B_STG)
#define SWZ_RC(r, c) ((uint32_t)((r) * 128 + (((c) ^ ((r) & 7)) << 4)))

__global__ void __launch_bounds__(512, 2) conv_mma(float* __restrict__ out) {
    extern __shared__ char smem[];
    const uint32_t sbase = smem_u32(smem);
    const int tid = threadIdx.x, wid = tid >> 5, lid = tid & 31;
    const int b  = blockIdx.y;
    const int q0 = blockIdx.x * 128;
    const int mwarp = wid >> 2, nwarp = wid & 3;

    const __half* xsrc = g_xt + (size_t)b * ROWSPAD * CIN;
    const __half* wsrc = g_wf + (size_t)b * 9 * COUT * CIN;

    float acc[2][8][4];
    #pragma unroll
    for (int mi = 0; mi < 2; mi++)
        #pragma unroll
        for (int ni = 0; ni < 8; ni++)
            #pragma unroll
            for (int e = 0; e < 4; e++) acc[mi][ni][e] = 0.f;

    // ---- A halo: 256 rows x 64 ci ----
    auto issueA = [&](int c4) {
        const int ci0 = c4 << 6;
        #pragma unroll
        for (int i = 0; i < 4; i++) {
            int j = tid + i * 512;
            int r = j >> 3, c = j & 7;
            const __half* src = xsrc + (size_t)(q0 + r) * CIN + ci0 + c * 8;
            CP_ASYNC16(sbase + SWZ_RC(r, c), src);
        }
        CP_COMMIT();
    };
    // ---- B stage: 256 n x 64 ci for (chunk, tap); s = c4*9 + t ----
    auto issueB = [&](int s) {
        const int c4 = s / 9, t = s - c4 * 9;
        const int ci0 = c4 << 6;
        const uint32_t stg = sbase + A_BYTES + (uint32_t)(s & 1) * B_STG;
        #pragma unroll
        for (int i = 0; i < 4; i++) {
            int j = tid + i * 512;
            int r = j >> 3, c = j & 7;
            const __half* src = wsrc + ((size_t)t * COUT + r) * CIN + ci0 + c * 8;
            CP_ASYNC16(stg + SWZ_RC(r, c), src);
        }
        CP_COMMIT();
    };

    issueA(0);
    issueB(0);

    const int lr = lid & 15, lc = lid >> 4;

    for (int s = 0; s < 36; s++) {
        const int c4 = s / 9, t = s - c4 * 9;
        if (t == 0 && s > 0) issueA(c4);          // prev chunk compute done
        if (s + 1 < 36) { issueB(s + 1); CP_WAIT1(); }
        else            { CP_WAIT0(); }
        __syncthreads();

        const int off = (t / 3 - 1) * PADW + (t % 3 - 1);
        const int arow0 = 64 + off + mwarp * 32;  // row in halo
        const uint32_t Bbuf = sbase + A_BYTES + (uint32_t)(s & 1) * B_STG;

        #pragma unroll
        for (int k16 = 0; k16 < 4; k16++) {
            uint32_t af[2][4];
            #pragma unroll
            for (int mi = 0; mi < 2; mi++) {
                int row = arow0 + mi * 16 + lr;
                uint32_t addr = sbase + row * 128 +
                                ((uint32_t)((k16 * 2 + lc) ^ (row & 7)) << 4);
                LDSM4(af[mi], addr);
            }
            uint32_t bf[4][4];
            #pragma unroll
            for (int ni = 0; ni < 4; ni++) {
                int row = nwarp * 64 + ni * 16 + lr;
                uint32_t addr = Bbuf + row * 128 +
                                ((uint32_t)((k16 * 2 + lc) ^ (row & 7)) << 4);
                LDSM4(bf[ni], addr);
            }
            #pragma unroll
            for (int mi = 0; mi < 2; mi++)
                #pragma unroll
                for (int ni = 0; ni < 4; ni++) {
                    MMA16816(acc[mi][2 * ni + 0], af[mi], bf[ni][0], bf[ni][2]);
                    MMA16816(acc[mi][2 * ni + 1], af[mi], bf[ni][1], bf[ni][3]);
                }
        }
        __syncthreads();
    }

    // ---- epilogue: scatter acc to out[b][cout][h*56+w] ----
    const int gr = lid >> 2, c2 = (lid & 3) * 2;
    float* outb = out + (size_t)b * COUT * HWSZ;
    #pragma unroll
    for (int mi = 0; mi < 2; mi++) {
        int qa = q0 + mwarp * 32 + mi * 16 + gr;
        int qb = qa + 8;
        int ha = qa / PADW - 1, wa = qa % PADW - 1;
        int hb = qb / PADW - 1, wb = qb % PADW - 1;
        bool va = ((unsigned)ha < HH) && ((unsigned)wa < WW);
        bool vb = ((unsigned)hb < HH) && ((unsigned)wb < WW);
        int pa = ha * WW + wa, pb = hb * WW + wb;
        #pragma unroll
        for (int ni = 0; ni < 8; ni++) {
            int n = nwarp * 64 + ni * 8 + c2;
            float* p = outb + (size_t)n * HWSZ;
            if (va) { p[pa] = acc[mi][ni][0]; p[HWSZ + pa] = acc[mi][ni][1]; }
            if (vb) { p[pb] = acc[mi][ni][2]; p[HWSZ + pb] = acc[mi][ni][3]; }
        }
    }
}

// ---------------------------------------------------------------------------
extern "C" void kernel_launch(void* const* d_in, const int* in_sizes, int n_in,
                              void* d_out, int out_size) {
    const float* x      = (const float*)d_in[0];  // (32,256,56,56)
    const float* att_w  = (const float*)d_in[1];  // (4,256)
    const float* weight = (const float*)d_in[2];  // (4,256,256,3,3)
    float* out = (float*)d_out;                   // (32,256,56,56)

    cudaFuncSetAttribute(conv_mma, cudaFuncAttributeMaxDynamicSharedMemorySize,
                         SMEM_BYTES_MMA);

    mean_kernel<<<BATCH * CIN, 256>>>(x);
    att_kernel<<<1, 128>>>(att_w);
    wprep_kernel<<<dim3(COUT, BATCH), 256>>>(weight);
    transpose_kernel<<<dim3(98, 4, BATCH), 256>>>(x);
    conv_mma<<<dim3(MTILES, BATCH), 512, SMEM_BYTES_MMA>>>(out);
}

// round 8
// speedup vs baseline: 3.1199x; 3.1199x over previous
#include <cuda_runtime.h>
#include <cuda_fp16.h>
#include <math.h>
#include <stdint.h>

#define BATCH 32
#define CIN   256
#define COUT  256
#define NEXP  4
#define HH    56
#define WW    56
#define HWSZ  3136

#define PADW    58
#define QCNT    3364           // 58*58 padded positions
#define GUARD   64
#define ROWSPAD 3712           // GUARD + 28*128 + GUARD
#define MTILES  27             // ceil(3364/128)

// ---------------------------------------------------------------------------
// Scratch (__device__ globals zero-initialized; guard/border rows stay 0)
// ---------------------------------------------------------------------------
__device__ float g_pooled[BATCH * CIN];
__device__ float g_att[BATCH * NEXP];
__device__ __half g_xt[(size_t)BATCH * ROWSPAD * CIN];
__device__ __half g_wf[(size_t)BATCH * 9 * COUT * CIN];

// ---------------------------------------------------------------------------
// PTX helpers (compute_80-era: valid on compute_103 base target)
// ---------------------------------------------------------------------------
__device__ __forceinline__ uint32_t smem_u32(const void* p) {
    uint32_t a;
    asm("{ .reg .u64 t; cvta.to.shared.u64 t, %1; cvt.u32.u64 %0, t; }"
        : "=r"(a) : "l"(p));
    return a;
}
#define CP_ASYNC16(dst, src) \
    asm volatile("cp.async.cg.shared.global [%0], [%1], 16;" \
                 :: "r"(dst), "l"(src) : "memory")
#define CP_COMMIT() asm volatile("cp.async.commit_group;" ::: "memory")
#define CP_WAIT0()  asm volatile("cp.async.wait_group 0;" ::: "memory")
#define CP_WAIT1()  asm volatile("cp.async.wait_group 1;" ::: "memory")

#define LDSM4(r, addr) \
    asm volatile("ldmatrix.sync.aligned.m8n8.x4.shared.b16 {%0,%1,%2,%3}, [%4];" \
                 : "=r"((r)[0]), "=r"((r)[1]), "=r"((r)[2]), "=r"((r)[3]) \
                 : "r"(addr))

#define MMA16816(d, a, b0, b1) \
    asm volatile("mma.sync.aligned.m16n8k16.row.col.f32.f16.f16.f32 " \
                 "{%0,%1,%2,%3}, {%4,%5,%6,%7}, {%8,%9}, {%0,%1,%2,%3};" \
                 : "+f"((d)[0]), "+f"((d)[1]), "+f"((d)[2]), "+f"((d)[3]) \
                 : "r"((a)[0]), "r"((a)[1]), "r"((a)[2]), "r"((a)[3]), \
                   "r"(b0), "r"(b1))

// ---------------------------------------------------------------------------
// Kernel 1: per-(b,c) spatial mean
// ---------------------------------------------------------------------------
__global__ void mean_kernel(const float* __restrict__ x) {
    int bc = blockIdx.x;
    const float4* p = reinterpret_cast<const float4*>(x + (size_t)bc * HWSZ);
    float s = 0.f;
    for (int i = threadIdx.x; i < HWSZ / 4; i += 256) {
        float4 v = p[i];
        s += (v.x + v.y) + (v.z + v.w);
    }
    #pragma unroll
    for (int o = 16; o; o >>= 1) s += __shfl_xor_sync(0xffffffffu, s, o);
    __shared__ float ws[8];
    if ((threadIdx.x & 31) == 0) ws[threadIdx.x >> 5] = s;
    __syncthreads();
    if (threadIdx.x == 0) {
        float t = 0.f;
        #pragma unroll
        for (int i = 0; i < 8; i++) t += ws[i];
        g_pooled[bc] = t * (1.0f / (float)HWSZ);
    }
}

// ---------------------------------------------------------------------------
// Kernel 2: att = sigmoid(pooled @ att_w^T)
// ---------------------------------------------------------------------------
__global__ void att_kernel(const float* __restrict__ att_w) {
    int idx = threadIdx.x;
    int b = idx >> 2, k = idx & 3;
    const float* pr = g_pooled + b * CIN;
    const float* wr = att_w + k * CIN;
    float s = 0.f;
    #pragma unroll 8
    for (int c = 0; c < CIN; c++) s += pr[c] * wr[c];
    g_att[idx] = 1.0f / (1.0f + expf(-s));
}

// ---------------------------------------------------------------------------
// Kernel 3: aggregate weights -> fp16, layout [b][t][cout][ci]
// ---------------------------------------------------------------------------
__global__ void wprep_kernel(const float* __restrict__ weight) {
    int o = blockIdx.x, b = blockIdx.y, ci = threadIdx.x;
    float a[NEXP];
    #pragma unroll
    for (int k = 0; k < NEXP; k++) a[k] = g_att[b * NEXP + k];
    #pragma unroll
    for (int t = 0; t < 9; t++) {
        float v = 0.f;
        #pragma unroll
        for (int k = 0; k < NEXP; k++)
            v += a[k] * weight[(((size_t)k * COUT + o) * CIN + ci) * 9 + t];
        size_t p = (((size_t)b * 9 + t) * COUT + o) * CIN + ci;
        g_wf[p] = __float2half_rn(v);
    }
}

// ---------------------------------------------------------------------------
// Kernel 4: transpose x -> padded position-major fp16
// ---------------------------------------------------------------------------
__global__ void __launch_bounds__(256) transpose_kernel(const float* __restrict__ x) {
    __shared__ float tile[64][33];
    int b   = blockIdx.z;
    int ci0 = blockIdx.y * 64;
    int p0  = blockIdx.x * 32;
    int tid = threadIdx.x;
    int px = tid & 31, cir = tid >> 5;
    #pragma unroll
    for (int i = 0; i < 8; i++) {
        int ci = cir * 8 + i;
        tile[ci][px] = x[((size_t)b * CIN + ci0 + ci) * HWSZ + p0 + px];
    }
    __syncthreads();
    int cc = tid & 7, r = tid >> 3;
    int p = p0 + r;
    int h = p / WW, w = p % WW;
    size_t row = (size_t)b * ROWSPAD + GUARD + (size_t)(h + 1) * PADW + (w + 1);
    __align__(16) __half h8[8];
    #pragma unroll
    for (int j = 0; j < 8; j++)
        h8[j] = __float2half_rn(tile[cc * 8 + j][r]);
    *reinterpret_cast<uint4*>(g_xt + row * CIN + ci0 + cc * 8) =
        *reinterpret_cast<const uint4*>(h8);
}

// ---------------------------------------------------------------------------
// Kernel 5: implicit-GEMM conv, pure fp16 mma.sync (single combo).
// CTA tile: M=128 positions x N=256 couts, 512 threads (16 warps = 4M x 4N).
// A (x) staged once per ci-chunk as a 256-row halo; all 9 taps are row
// offsets into the resident halo. B (w) double-buffered per (chunk,tap).
// SMEM: A 32KB | B 2x32KB = 96KB. 1 CTA/SM — NO reg cap (R7 lesson:
// launch_bounds(512,2) forced 64 regs and spilled the accumulators).
// ---------------------------------------------------------------------------
#define A_BYTES   32768
#define B_STG     32768
#define SMEM_BYTES_MMA (A_BYTES + 2 * B_STG)
#define SWZ_RC(r, c) ((uint32_t)((r) * 128 + (((c) ^ ((r) & 7)) << 4)))

__global__ void __launch_bounds__(512, 1) conv_mma(float* __restrict__ out) {
    extern __shared__ char smem[];
    const uint32_t sbase = smem_u32(smem);
    const int tid = threadIdx.x, wid = tid >> 5, lid = tid & 31;
    const int b  = blockIdx.y;
    const int q0 = blockIdx.x * 128;
    const int mwarp = wid >> 2, nwarp = wid & 3;

    const __half* xsrc = g_xt + (size_t)b * ROWSPAD * CIN;
    const __half* wsrc = g_wf + (size_t)b * 9 * COUT * CIN;

    float acc[2][8][4];
    #pragma unroll
    for (int mi = 0; mi < 2; mi++)
        #pragma unroll
        for (int ni = 0; ni < 8; ni++)
            #pragma unroll
            for (int e = 0; e < 4; e++) acc[mi][ni][e] = 0.f;

    // ---- A halo: 256 rows x 64 ci ----
    auto issueA = [&](int c4) {
        const int ci0 = c4 << 6;
        #pragma unroll
        for (int i = 0; i < 4; i++) {
            int j = tid + i * 512;
            int r = j >> 3, c = j & 7;
            const __half* src = xsrc + (size_t)(q0 + r) * CIN + ci0 + c * 8;
            CP_ASYNC16(sbase + SWZ_RC(r, c), src);
        }
        CP_COMMIT();
    };
    // ---- B stage: 256 n x 64 ci for (chunk, tap); s = c4*9 + t ----
    auto issueB = [&](int s) {
        const int c4 = s / 9, t = s - c4 * 9;
        const int ci0 = c4 << 6;
        const uint32_t stg = sbase + A_BYTES + (uint32_t)(s & 1) * B_STG;
        #pragma unroll
        for (int i = 0; i < 4; i++) {
            int j = tid + i * 512;
            int r = j >> 3, c = j & 7;
            const __half* src = wsrc + ((size_t)t * COUT + r) * CIN + ci0 + c * 8;
            CP_ASYNC16(stg + SWZ_RC(r, c), src);
        }
        CP_COMMIT();
    };

    issueA(0);
    issueB(0);

    const int lr = lid & 15, lc = lid >> 4;

    for (int s = 0; s < 36; s++) {
        const int c4 = s / 9, t = s - c4 * 9;
        if (t == 0 && s > 0) issueA(c4);          // prev chunk compute done
        if (s + 1 < 36) { issueB(s + 1); CP_WAIT1(); }
        else            { CP_WAIT0(); }
        __syncthreads();

        const int off = (t / 3 - 1) * PADW + (t % 3 - 1);
        const int arow0 = 64 + off + mwarp * 32;  // row in halo
        const uint32_t Bbuf = sbase + A_BYTES + (uint32_t)(s & 1) * B_STG;

        #pragma unroll
        for (int k16 = 0; k16 < 4; k16++) {
            uint32_t af[2][4];
            #pragma unroll
            for (int mi = 0; mi < 2; mi++) {
                int row = arow0 + mi * 16 + lr;
                uint32_t addr = sbase + row * 128 +
                                ((uint32_t)((k16 * 2 + lc) ^ (row & 7)) << 4);
                LDSM4(af[mi], addr);
            }
            uint32_t bf[4][4];
            #pragma unroll
            for (int ni = 0; ni < 4; ni++) {
                int row = nwarp * 64 + ni * 16 + lr;
                uint32_t addr = Bbuf + row * 128 +
                                ((uint32_t)((k16 * 2 + lc) ^ (row & 7)) << 4);
                LDSM4(bf[ni], addr);
            }
            #pragma unroll
            for (int mi = 0; mi < 2; mi++)
                #pragma unroll
                for (int ni = 0; ni < 4; ni++) {
                    MMA16816(acc[mi][2 * ni + 0], af[mi], bf[ni][0], bf[ni][2]);
                    MMA16816(acc[mi][2 * ni + 1], af[mi], bf[ni][1], bf[ni][3]);
                }
        }
        __syncthreads();
    }

    // ---- epilogue: scatter acc to out[b][cout][h*56+w] ----
    const int gr = lid >> 2, c2 = (lid & 3) * 2;
    float* outb = out + (size_t)b * COUT * HWSZ;
    #pragma unroll
    for (int mi = 0; mi < 2; mi++) {
        int qa = q0 + mwarp * 32 + mi * 16 + gr;
        int qb = qa + 8;
        int ha = qa / PADW - 1, wa = qa % PADW - 1;
        int hb = qb / PADW - 1, wb = qb % PADW - 1;
        bool va = ((unsigned)ha < HH) && ((unsigned)wa < WW);
        bool vb = ((unsigned)hb < HH) && ((unsigned)wb < WW);
        int pa = ha * WW + wa, pb = hb * WW + wb;
        #pragma unroll
        for (int ni = 0; ni < 8; ni++) {
            int n = nwarp * 64 + ni * 8 + c2;
            float* p = outb + (size_t)n * HWSZ;
            if (va) { p[pa] = acc[mi][ni][0]; p[HWSZ + pa] = acc[mi][ni][1]; }
            if (vb) { p[pb] = acc[mi][ni][2]; p[HWSZ + pb] = acc[mi][ni][3]; }
        }
    }
}

// ---------------------------------------------------------------------------
extern "C" void kernel_launch(void* const* d_in, const int* in_sizes, int n_in,
                              void* d_out, int out_size) {
    const float* x      = (const float*)d_in[0];  // (32,256,56,56)
    const float* att_w  = (const float*)d_in[1];  // (4,256)
    const float* weight = (const float*)d_in[2];  // (4,256,256,3,3)
    float* out = (float*)d_out;                   // (32,256,56,56)

    cudaFuncSetAttribute(conv_mma, cudaFuncAttributeMaxDynamicSharedMemorySize,
                         SMEM_BYTES_MMA);

    mean_kernel<<<BATCH * CIN, 256>>>(x);
    att_kernel<<<1, 128>>>(att_w);
    wprep_kernel<<<dim3(COUT, BATCH), 256>>>(weight);
    transpose_kernel<<<dim3(98, 4, BATCH), 256>>>(x);
    conv_mma<<<dim3(MTILES, BATCH), 512, SMEM_BYTES_MMA>>>(out);
}